// round 14
// baseline (speedup 1.0000x reference)
#include <cuda_runtime.h>
#include <cuda_fp16.h>
#include <cstdint>
#include <math.h>

#define BSZ 128
#define SSZ 256
#define ISZ 1024
#define HSZ 1024
#define G4  4096
#define CSZ 1000

#define GRID2 128

// ---------------------------------------------------------------------------
// Device-global scratch
// ---------------------------------------------------------------------------
__device__ __half g_xw[(size_t)SSZ * G4 * BSZ];       // [s][g][b] fp16
__device__ __half g_xh[(size_t)BSZ * SSZ * ISZ];      // x rounded fp16 [b][s][k]
__device__ __half g_wxh[(size_t)G4 * ISZ];            // Wxh rounded fp16
__device__ __half g_whh[(size_t)G4 * HSZ];            // Whh rounded fp16
__device__ __half g_h[2][BSZ * HSZ];                  // h ping-pong fp16 [b][k]
__device__ unsigned g_flag[2][8];                     // per (mh, chunk) producer counters

// ---------------------------------------------------------------------------
// PTX helpers
// ---------------------------------------------------------------------------
__device__ __forceinline__ uint32_t smem_u32(const void* p) {
    uint32_t a;
    asm("{ .reg .u64 t; cvta.to.shared.u64 t, %1; cvt.u32.u64 %0, t; }"
        : "=r"(a) : "l"(p));
    return a;
}

#define CP16(s, g) \
    asm volatile("cp.async.cg.shared.global [%0], [%1], 16;" :: "r"(s), "l"(g))
#define CP_COMMIT() asm volatile("cp.async.commit_group;" ::: "memory")
#define CP_WAIT1()  asm volatile("cp.async.wait_group 1;" ::: "memory")
#define CP_WAIT0()  asm volatile("cp.async.wait_group 0;" ::: "memory")

__device__ __forceinline__ void ldmx4(uint32_t* r, uint32_t addr) {
    asm volatile("ldmatrix.sync.aligned.m8n8.x4.shared.b16 {%0,%1,%2,%3}, [%4];"
        : "=r"(r[0]), "=r"(r[1]), "=r"(r[2]), "=r"(r[3]) : "r"(addr));
}

__device__ __forceinline__ void mma16816(float* d, const uint32_t* a, const uint32_t* b) {
    asm volatile(
        "mma.sync.aligned.m16n8k16.row.col.f32.f16.f16.f32 "
        "{%0,%1,%2,%3}, {%4,%5,%6,%7}, {%8,%9}, {%0,%1,%2,%3};"
        : "+f"(d[0]), "+f"(d[1]), "+f"(d[2]), "+f"(d[3])
        : "r"(a[0]), "r"(a[1]), "r"(a[2]), "r"(a[3]), "r"(b[0]), "r"(b[1]));
}

__device__ __forceinline__ float sigf(float x) { return 1.0f / (1.0f + __expf(-x)); }
__device__ __forceinline__ float tanh_fast(float x) {
    float e = __expf(fminf(fmaxf(2.0f * x, -30.0f), 30.0f));
    return __fdividef(e - 1.0f, e + 1.0f);
}

// ---------------------------------------------------------------------------
// round fp32 -> fp16
// ---------------------------------------------------------------------------
__global__ void round_h16(const float* __restrict__ src, int sel, int n4) {
    __half* dst = (sel == 0) ? g_xh : (sel == 1) ? g_wxh : g_whh;
    int i = blockIdx.x * blockDim.x + threadIdx.x;
    if (i >= n4) return;
    float4 v = reinterpret_cast<const float4*>(src)[i];
    __half2 a, b;
    a.x = __float2half_rn(v.x); a.y = __float2half_rn(v.y);
    b.x = __float2half_rn(v.z); b.y = __float2half_rn(v.w);
    reinterpret_cast<__half2*>(dst)[2 * i]     = a;
    reinterpret_cast<__half2*>(dst)[2 * i + 1] = b;
}

__global__ void init_state() {
    int i = blockIdx.x * blockDim.x + threadIdx.x;
    if (i < BSZ * HSZ) g_h[0][i] = __float2half(0.0f);
}

// ---------------------------------------------------------------------------
// Phase 1: xw[s][g][b] (fp16), M=128 (batch), N=128 gates/CTA, K=1024, 16 chunks.
// (unchanged from R13 -- at the HMMA.f32 roofline)
// ---------------------------------------------------------------------------
#define PITCH     144
#define P1_STG    36864
#define P1_BOFF   18432
#define P1_BIAS   110592
#define P1_SMEM   111104
#define NCHUNK    16

__global__ __launch_bounds__(256, 1) void gemm_xw_tc(const float* __restrict__ bxh,
                                                     const float* __restrict__ bhh) {
    extern __shared__ char sm[];
    const uint32_t sb = smem_u32(sm);
    const int tid = threadIdx.x;
    const int wid = tid >> 5, lane = tid & 31;
    const int s  = blockIdx.y;
    const int n0 = blockIdx.x * 128;

    float* sbias = reinterpret_cast<float*>(sm + P1_BIAS);
    if (tid < 128) sbias[tid] = bxh[n0 + tid] + bhh[n0 + tid];

    const int wm = wid >> 2, wn = wid & 3;
    const int lrow = tid >> 3, lq = tid & 7;

    auto load_stage = [&](int c, int buf) {
        const int koff = c * 64 + lq * 8;
        uint32_t Ab = sb + buf * P1_STG + lrow * PITCH + lq * 16;
        uint32_t Bb = Ab + P1_BOFF;
#pragma unroll
        for (int i = 0; i < 4; i++) {
            int row = lrow + i * 32;
            CP16(Ab + i * 32 * PITCH, g_xh + (((size_t)((row << 8) + s)) << 10) + koff);
            CP16(Bb + i * 32 * PITCH, g_wxh + (((size_t)(n0 + row)) << 10) + koff);
        }
    };

    load_stage(0, 0); CP_COMMIT();
    load_stage(1, 1); CP_COMMIT();

    float d[4][4][4];
#pragma unroll
    for (int i = 0; i < 4; i++)
#pragma unroll
        for (int j = 0; j < 4; j++)
#pragma unroll
            for (int k = 0; k < 4; k++) d[i][j][k] = 0.0f;

    const uint32_t a_r = (uint32_t)(lane & 15) * PITCH + ((lane >> 4) << 4);
    const uint32_t b_r = (uint32_t)((lane & 7) + ((lane & 16) >> 1)) * PITCH
                       + (((lane >> 3) & 1) << 4);

    int buf = 0;
    for (int c = 0; c < NCHUNK; c++) {
        CP_WAIT1();
        __syncthreads();
        if (c + 2 < NCHUNK) load_stage(c + 2, (c + 2) % 3);
        CP_COMMIT();
        const uint32_t Ab = sb + buf * P1_STG;
        const uint32_t Bb = Ab + P1_BOFF;
#pragma unroll
        for (int s2 = 0; s2 < 4; s2++) {
            uint32_t a[4][4], b[2][4];
#pragma unroll
            for (int mt = 0; mt < 4; mt++)
                ldmx4(a[mt], Ab + (uint32_t)(wm * 64 + mt * 16) * PITCH + s2 * 32 + a_r);
#pragma unroll
            for (int nt = 0; nt < 2; nt++)
                ldmx4(b[nt], Bb + (uint32_t)(wn * 32 + nt * 16) * PITCH + s2 * 32 + b_r);
#pragma unroll
            for (int mt = 0; mt < 4; mt++)
#pragma unroll
                for (int n8 = 0; n8 < 4; n8++)
                    mma16816(d[mt][n8], a[mt], &b[n8 >> 1][(n8 & 1) * 2]);
        }
        buf = (buf == 2) ? 0 : buf + 1;
    }

    // epilogue: transpose through smem, fp16 writeout with bias
    __syncthreads();
    float* tile = reinterpret_cast<float*>(sm);  // [g:128][pitch 132]
    const int fr = lane >> 2, fc = (lane & 3) * 2;
#pragma unroll
    for (int mt = 0; mt < 4; mt++)
#pragma unroll
        for (int n8 = 0; n8 < 4; n8++) {
            int r0 = wm * 64 + mt * 16 + fr;
            int cc = wn * 32 + n8 * 8 + fc;
            tile[(size_t)cc * 132 + r0]           = d[mt][n8][0];
            tile[(size_t)(cc + 1) * 132 + r0]     = d[mt][n8][1];
            tile[(size_t)cc * 132 + r0 + 8]       = d[mt][n8][2];
            tile[(size_t)(cc + 1) * 132 + r0 + 8] = d[mt][n8][3];
        }
    __syncthreads();
#pragma unroll
    for (int it = 0; it < 8; it++) {
        int u = tid + it * 256;          // 2048 stores of 8 halves
        int g = u >> 4, q = u & 15;
        const float* src = tile + (size_t)g * 132 + q * 8;
        float bi = sbias[g];
        __align__(16) __half h8[8];
#pragma unroll
        for (int i = 0; i < 8; i++) h8[i] = __float2half_rn(src[i] + bi);
        *reinterpret_cast<uint4*>(g_xw + ((size_t)s * G4 + n0 + g) * BSZ + q * 8) =
            *reinterpret_cast<const uint4*>(h8);
    }
}

// ---------------------------------------------------------------------------
// Phase 2: PERSISTENT recurrence with PER-CHUNK PRODUCER FLAGS (no grid barrier).
// 128 CTAs: j = bid>>1 (16 hidden cols), mh = bid&1 (batch half).
// h-chunk c of half mh is produced by the 8 CTAs with bid>>4==c, bid&1==mh;
// they bump g_flag[mh][c] by 1 each after writing h. Consumers poll
// flag >= base + 8*t before loading chunk c for step t. The two mh halves are
// fully decoupled; producer skew is pipelined into the consumer mainloop.
// Everything else identical to R13 (8 chunks of 128, 3 A-buffers WAIT1,
// resident Whh, fp16 xw double-buffered, c in registers).
// smem: B 0..139264 | A 139264 (3x17408) | XW 191488 (2x8192) = 207872
// epilogue overlays: sg f32[64][65] @A buf0, sh f32[64][16] @A buf2
// ---------------------------------------------------------------------------
#define PITCH2   272
#define PB_STG   17408
#define PA_OFF   139264
#define PXW_OFF  191488
#define P2_SMEM  207872
#define NCH2     8

__global__ __launch_bounds__(256, 1) void lstm_persist() {
    extern __shared__ char sm[];
    const uint32_t sb = smem_u32(sm);
    const int tid = threadIdx.x;
    const int wid = tid >> 5, lane = tid & 31;
    const int bid = blockIdx.x;
    const int j  = bid >> 1;
    const int mh = bid & 1;
    const int jc = j >> 3;          // this CTA's producer chunk group

    const int wm = wid >> 2, gi = wid & 3;
    const int lrow = tid >> 4, lq = tid & 15;   // 16 rows x 16 quads

    const uint32_t a_r = (uint32_t)(lane & 15) * PITCH2 + ((lane >> 4) << 4);
    const uint32_t b_r = (uint32_t)((lane & 7) + ((lane & 16) >> 1)) * PITCH2
                       + (((lane >> 3) & 1) << 4);

    // flag baselines (accumulating counters survive graph replays; reading a
    // possibly-advanced base only makes waits stricter, never unsafe)
    __shared__ unsigned s_fbase[8];
    if (tid < 8) s_fbase[tid] = *(volatile unsigned*)&g_flag[mh][tid];

    auto xw_load = [&](int t, int slot) {
#pragma unroll
        for (int it = 0; it < 2; it++) {
            int u = tid + it * 256;          // 512 CP16 = 8KB fp16 slice
            int r = u >> 3, q = u & 7;
            const __half* src = g_xw
                + ((size_t)t * G4 + (r >> 4) * HSZ + j * 16 + (r & 15)) * BSZ
                + mh * 64 + q * 8;
            CP16(sb + PXW_OFF + slot * 8192 + r * 128 + q * 16, src);
        }
    };

    // per-warp wait: lane 0 polls the producer counter, then syncwarp.
    auto wait_flag = [&](int c, int t) {
        if (lane == 0) {
            unsigned target = s_fbase[c] + 8u * (unsigned)t;
            while ((int)(*(volatile unsigned*)&g_flag[mh][c] - target) < 0)
                __nanosleep(32);
        }
        __syncwarp();
    };

    // ---- one-time: resident Whh slice (8 chunks) + xw(0) ----
    for (int c = 0; c < NCH2; c++) {
        const int koff = c * 128 + lq * 8;
        uint32_t Sb = sb + c * PB_STG + lrow * PITCH2 + lq * 16;
#pragma unroll
        for (int i = 0; i < 4; i++) {
            int row = lrow + i * 16;
            int grow = (row >> 4) * HSZ + j * 16 + (row & 15);
            CP16(Sb + i * 16 * PITCH2, g_whh + ((size_t)grow << 10) + koff);
        }
    }
    xw_load(0, 0);
    CP_COMMIT();
    CP_WAIT0();
    __syncthreads();   // also publishes s_fbase

    // cell state in registers: thread owns (bl, hq) -> 4 hidden cols
    const int bl = tid & 63, hq = tid >> 6;
    float cre[4] = {0.0f, 0.0f, 0.0f, 0.0f};

    float* sg = reinterpret_cast<float*>(sm + PA_OFF);                 // A buf0
    float* sh = reinterpret_cast<float*>(sm + PA_OFF + 2 * PB_STG);    // A buf2

    for (int t = 0; t < SSZ; t++) {
        const __half* __restrict__ hin = g_h[t & 1];
        __half* __restrict__ hout = g_h[(t + 1) & 1];

        auto loadA = [&](int c, int buf) {
            const int koff = c * 128 + lq * 8;
            uint32_t Sb = sb + PA_OFF + buf * PB_STG + lrow * PITCH2 + lq * 16;
#pragma unroll
            for (int i = 0; i < 4; i++) {
                int row = lrow + i * 16;
                CP16(Sb + i * 16 * PITCH2, hin + ((size_t)(mh * 64 + row) << 10) + koff);
            }
        };

        if (t > 0) wait_flag(0, t);
        loadA(0, 0); CP_COMMIT();
        if (t > 0) wait_flag(1, t);
        loadA(1, 1); CP_COMMIT();

        float d[2][2][4];
#pragma unroll
        for (int i = 0; i < 2; i++)
#pragma unroll
            for (int jj = 0; jj < 2; jj++)
#pragma unroll
                for (int k = 0; k < 4; k++) d[i][jj][k] = 0.0f;

        int buf = 0;
        for (int c = 0; c < NCH2; c++) {
            CP_WAIT1();
            __syncthreads();
            if (c + 2 < NCH2) {
                if (t > 0) wait_flag(c + 2, t);
                loadA(c + 2, (c + 2) % 3);
            }
            if (c == 0 && t + 1 < SSZ) xw_load(t + 1, (t + 1) & 1);
            CP_COMMIT();
            const uint32_t Hb = sb + PA_OFF + buf * PB_STG;
            const uint32_t Bb = sb + c * PB_STG;     // resident Whh chunk c
#pragma unroll
            for (int s2 = 0; s2 < 8; s2++) {
                uint32_t a[2][4], b[4];
#pragma unroll
                for (int mt = 0; mt < 2; mt++)
                    ldmx4(a[mt], Hb + (uint32_t)(wm * 32 + mt * 16) * PITCH2 + s2 * 32 + a_r);
                ldmx4(b, Bb + (uint32_t)(gi * 16) * PITCH2 + s2 * 32 + b_r);
#pragma unroll
                for (int mt = 0; mt < 2; mt++)
#pragma unroll
                    for (int n8 = 0; n8 < 2; n8++)
                        mma16816(d[mt][n8], a[mt], &b[n8 * 2]);
            }
            buf = (buf == 2) ? 0 : buf + 1;
        }

        // gates to smem: sg[b][gate*16+hc] in A-buf0 (chunk 7 reads buf1)
        const int fr = lane >> 2, fc = (lane & 3) * 2;
#pragma unroll
        for (int mt = 0; mt < 2; mt++)
#pragma unroll
            for (int n8 = 0; n8 < 2; n8++) {
                int r0 = wm * 32 + mt * 16 + fr;
                int cc = gi * 16 + n8 * 8 + fc;
                sg[(size_t)r0 * 65 + cc]           = d[mt][n8][0];
                sg[(size_t)r0 * 65 + cc + 1]       = d[mt][n8][1];
                sg[(size_t)(r0 + 8) * 65 + cc]     = d[mt][n8][2];
                sg[(size_t)(r0 + 8) * 65 + cc + 1] = d[mt][n8][3];
            }
        __syncthreads();

        // fused gate math; c in registers; xw from fp16 smem slot t&1
        const __half* sxwh = reinterpret_cast<const __half*>(sm + PXW_OFF + (t & 1) * 8192);
#pragma unroll
        for (int ii = 0; ii < 4; ii++) {
            const int hc = hq * 4 + ii;
            const size_t ix = (size_t)bl * 65 + hc;
            float vi = sg[ix]      + __half2float(sxwh[(0 * 16 + hc) * 64 + bl]);
            float vf = sg[ix + 16] + __half2float(sxwh[(1 * 16 + hc) * 64 + bl]);
            float vg = sg[ix + 32] + __half2float(sxwh[(2 * 16 + hc) * 64 + bl]);
            float vo = sg[ix + 48] + __half2float(sxwh[(3 * 16 + hc) * 64 + bl]);
            float ig = sigf(vi), fg = sigf(vf), og = sigf(vo);
            float ch = tanh_fast(vg);
            float cn = cre[ii] * fg + ig * ch;
            cre[ii] = cn;
            sh[bl * 16 + hc] = og * tanh_fast(cn);
        }
        __syncthreads();

        // h writeout: fp16, 16B stores
        if (tid < 128) {
            const int b = tid >> 1, half = tid & 1;
            const float* src = sh + b * 16 + half * 8;
            __align__(16) __half h8[8];
#pragma unroll
            for (int i = 0; i < 8; i++) h8[i] = __float2half_rn(src[i]);
            size_t dst = ((size_t)(mh * 64 + b) << 10) + j * 16 + half * 8;
            *reinterpret_cast<uint4*>(hout + dst) = *reinterpret_cast<const uint4*>(h8);
        }

        // release: every thread fences its own stores, then one arrive per CTA
        __threadfence();
        __syncthreads();
        if (tid == 0 && t + 1 < SSZ)
            atomicAdd(&g_flag[mh][jc], 1u);
    }
}

// ---------------------------------------------------------------------------
// Phase 3: out[b][c] = h_last . Wfc[c] + bfc[c]
// ---------------------------------------------------------------------------
__global__ __launch_bounds__(256) void fc_out(const float* __restrict__ Wfc,
                                              const float* __restrict__ bfc,
                                              float* __restrict__ out) {
    __shared__ float hs[HSZ];
    const int b = blockIdx.x;
    for (int i = threadIdx.x; i < HSZ; i += 256)
        hs[i] = __half2float(g_h[0][b * HSZ + i]);
    __syncthreads();

    for (int cc = threadIdx.x; cc < CSZ; cc += 256) {
        const float* wr = Wfc + (size_t)cc * HSZ;
        float acc = 0.0f;
#pragma unroll 4
        for (int k = 0; k < HSZ; k += 4) {
            float4 w = *reinterpret_cast<const float4*>(wr + k);
            acc = fmaf(hs[k + 0], w.x, acc);
            acc = fmaf(hs[k + 1], w.y, acc);
            acc = fmaf(hs[k + 2], w.z, acc);
            acc = fmaf(hs[k + 3], w.w, acc);
        }
        out[b * CSZ + cc] = acc + bfc[cc];
    }
}

// ---------------------------------------------------------------------------
// launch
// ---------------------------------------------------------------------------
extern "C" void kernel_launch(void* const* d_in, const int* in_sizes, int n_in,
                              void* d_out, int out_size) {
    const float* x   = (const float*)d_in[0];
    const float* Wxh = (const float*)d_in[1];
    const float* bxh = (const float*)d_in[2];
    const float* Whh = (const float*)d_in[3];
    const float* bhh = (const float*)d_in[4];
    const float* Wfc = (const float*)d_in[5];
    const float* bfc = (const float*)d_in[6];
    float* out = (float*)d_out;

    cudaFuncSetAttribute(gemm_xw_tc,   cudaFuncAttributeMaxDynamicSharedMemorySize, P1_SMEM);
    cudaFuncSetAttribute(lstm_persist, cudaFuncAttributeMaxDynamicSharedMemorySize, P2_SMEM);

    {
        int n4 = (BSZ * SSZ * ISZ) / 4;
        round_h16<<<(n4 + 255) / 256, 256>>>(x, 0, n4);
        n4 = (G4 * ISZ) / 4;
        round_h16<<<(n4 + 255) / 256, 256>>>(Wxh, 1, n4);
        n4 = (G4 * HSZ) / 4;
        round_h16<<<(n4 + 255) / 256, 256>>>(Whh, 2, n4);
    }
    init_state<<<(BSZ * HSZ + 255) / 256, 256>>>();

    dim3 g1(G4 / 128, SSZ);   // (32, 256)
    gemm_xw_tc<<<g1, 256, P1_SMEM>>>(bxh, bhh);

    lstm_persist<<<GRID2, 256, P2_SMEM>>>();

    fc_out<<<BSZ, 256>>>(Wfc, bfc, out);
}

// round 15
// speedup vs baseline: 1.1784x; 1.1784x over previous
#include <cuda_runtime.h>
#include <cuda_fp16.h>
#include <cstdint>
#include <math.h>

#define BSZ 128
#define SSZ 256
#define ISZ 1024
#define HSZ 1024
#define G4  4096
#define CSZ 1000

#define GRID2 128
#define HALF2 64     // CTAs per batch-half barrier

// ---------------------------------------------------------------------------
// Device-global scratch
// ---------------------------------------------------------------------------
__device__ __half g_xw[(size_t)SSZ * G4 * BSZ];       // [s][g][b] fp16
__device__ __half g_xh[(size_t)BSZ * SSZ * ISZ];      // x rounded fp16 [b][s][k]
__device__ __half g_wxh[(size_t)G4 * ISZ];            // Wxh rounded fp16
__device__ __half g_whh[(size_t)G4 * HSZ];            // Whh rounded fp16
__device__ __half g_h[2][BSZ * HSZ];                  // h ping-pong fp16 [b][k]
__device__ unsigned g_bar_count[2];                   // per-half barrier (bss)
__device__ unsigned g_bar_gen[2];

// ---------------------------------------------------------------------------
// PTX helpers
// ---------------------------------------------------------------------------
__device__ __forceinline__ uint32_t smem_u32(const void* p) {
    uint32_t a;
    asm("{ .reg .u64 t; cvta.to.shared.u64 t, %1; cvt.u32.u64 %0, t; }"
        : "=r"(a) : "l"(p));
    return a;
}

#define CP16(s, g) \
    asm volatile("cp.async.cg.shared.global [%0], [%1], 16;" :: "r"(s), "l"(g))
#define CP_COMMIT() asm volatile("cp.async.commit_group;" ::: "memory")
#define CP_WAIT1()  asm volatile("cp.async.wait_group 1;" ::: "memory")
#define CP_WAIT0()  asm volatile("cp.async.wait_group 0;" ::: "memory")

__device__ __forceinline__ void ldmx4(uint32_t* r, uint32_t addr) {
    asm volatile("ldmatrix.sync.aligned.m8n8.x4.shared.b16 {%0,%1,%2,%3}, [%4];"
        : "=r"(r[0]), "=r"(r[1]), "=r"(r[2]), "=r"(r[3]) : "r"(addr));
}

__device__ __forceinline__ void mma16816(float* d, const uint32_t* a, const uint32_t* b) {
    asm volatile(
        "mma.sync.aligned.m16n8k16.row.col.f32.f16.f16.f32 "
        "{%0,%1,%2,%3}, {%4,%5,%6,%7}, {%8,%9}, {%0,%1,%2,%3};"
        : "+f"(d[0]), "+f"(d[1]), "+f"(d[2]), "+f"(d[3])
        : "r"(a[0]), "r"(a[1]), "r"(a[2]), "r"(a[3]), "r"(b[0]), "r"(b[1]));
}

__device__ __forceinline__ float sigf(float x) { return 1.0f / (1.0f + __expf(-x)); }
__device__ __forceinline__ float tanh_fast(float x) {
    float e = __expf(fminf(fmaxf(2.0f * x, -30.0f), 30.0f));
    return __fdividef(e - 1.0f, e + 1.0f);
}

// ---------------------------------------------------------------------------
// round fp32 -> fp16
// ---------------------------------------------------------------------------
__global__ void round_h16(const float* __restrict__ src, int sel, int n4) {
    __half* dst = (sel == 0) ? g_xh : (sel == 1) ? g_wxh : g_whh;
    int i = blockIdx.x * blockDim.x + threadIdx.x;
    if (i >= n4) return;
    float4 v = reinterpret_cast<const float4*>(src)[i];
    __half2 a, b;
    a.x = __float2half_rn(v.x); a.y = __float2half_rn(v.y);
    b.x = __float2half_rn(v.z); b.y = __float2half_rn(v.w);
    reinterpret_cast<__half2*>(dst)[2 * i]     = a;
    reinterpret_cast<__half2*>(dst)[2 * i + 1] = b;
}

__global__ void init_state() {
    int i = blockIdx.x * blockDim.x + threadIdx.x;
    if (i < BSZ * HSZ) g_h[0][i] = __float2half(0.0f);
}

// ---------------------------------------------------------------------------
// Phase 1: xw[s][g][b] (fp16), M=128 (batch), N=128 gates/CTA, K=1024, 16 chunks.
// (unchanged -- at the HMMA.f32 roofline)
// ---------------------------------------------------------------------------
#define PITCH     144
#define P1_STG    36864
#define P1_BOFF   18432
#define P1_BIAS   110592
#define P1_SMEM   111104
#define NCHUNK    16

__global__ __launch_bounds__(256, 1) void gemm_xw_tc(const float* __restrict__ bxh,
                                                     const float* __restrict__ bhh) {
    extern __shared__ char sm[];
    const uint32_t sb = smem_u32(sm);
    const int tid = threadIdx.x;
    const int wid = tid >> 5, lane = tid & 31;
    const int s  = blockIdx.y;
    const int n0 = blockIdx.x * 128;

    float* sbias = reinterpret_cast<float*>(sm + P1_BIAS);
    if (tid < 128) sbias[tid] = bxh[n0 + tid] + bhh[n0 + tid];

    const int wm = wid >> 2, wn = wid & 3;
    const int lrow = tid >> 3, lq = tid & 7;

    auto load_stage = [&](int c, int buf) {
        const int koff = c * 64 + lq * 8;
        uint32_t Ab = sb + buf * P1_STG + lrow * PITCH + lq * 16;
        uint32_t Bb = Ab + P1_BOFF;
#pragma unroll
        for (int i = 0; i < 4; i++) {
            int row = lrow + i * 32;
            CP16(Ab + i * 32 * PITCH, g_xh + (((size_t)((row << 8) + s)) << 10) + koff);
            CP16(Bb + i * 32 * PITCH, g_wxh + (((size_t)(n0 + row)) << 10) + koff);
        }
    };

    load_stage(0, 0); CP_COMMIT();
    load_stage(1, 1); CP_COMMIT();

    float d[4][4][4];
#pragma unroll
    for (int i = 0; i < 4; i++)
#pragma unroll
        for (int j = 0; j < 4; j++)
#pragma unroll
            for (int k = 0; k < 4; k++) d[i][j][k] = 0.0f;

    const uint32_t a_r = (uint32_t)(lane & 15) * PITCH + ((lane >> 4) << 4);
    const uint32_t b_r = (uint32_t)((lane & 7) + ((lane & 16) >> 1)) * PITCH
                       + (((lane >> 3) & 1) << 4);

    int buf = 0;
    for (int c = 0; c < NCHUNK; c++) {
        CP_WAIT1();
        __syncthreads();
        if (c + 2 < NCHUNK) load_stage(c + 2, (c + 2) % 3);
        CP_COMMIT();
        const uint32_t Ab = sb + buf * P1_STG;
        const uint32_t Bb = Ab + P1_BOFF;
#pragma unroll
        for (int s2 = 0; s2 < 4; s2++) {
            uint32_t a[4][4], b[2][4];
#pragma unroll
            for (int mt = 0; mt < 4; mt++)
                ldmx4(a[mt], Ab + (uint32_t)(wm * 64 + mt * 16) * PITCH + s2 * 32 + a_r);
#pragma unroll
            for (int nt = 0; nt < 2; nt++)
                ldmx4(b[nt], Bb + (uint32_t)(wn * 32 + nt * 16) * PITCH + s2 * 32 + b_r);
#pragma unroll
            for (int mt = 0; mt < 4; mt++)
#pragma unroll
                for (int n8 = 0; n8 < 4; n8++)
                    mma16816(d[mt][n8], a[mt], &b[n8 >> 1][(n8 & 1) * 2]);
        }
        buf = (buf == 2) ? 0 : buf + 1;
    }

    // epilogue: transpose through smem, fp16 writeout with bias
    __syncthreads();
    float* tile = reinterpret_cast<float*>(sm);  // [g:128][pitch 132]
    const int fr = lane >> 2, fc = (lane & 3) * 2;
#pragma unroll
    for (int mt = 0; mt < 4; mt++)
#pragma unroll
        for (int n8 = 0; n8 < 4; n8++) {
            int r0 = wm * 64 + mt * 16 + fr;
            int cc = wn * 32 + n8 * 8 + fc;
            tile[(size_t)cc * 132 + r0]           = d[mt][n8][0];
            tile[(size_t)(cc + 1) * 132 + r0]     = d[mt][n8][1];
            tile[(size_t)cc * 132 + r0 + 8]       = d[mt][n8][2];
            tile[(size_t)(cc + 1) * 132 + r0 + 8] = d[mt][n8][3];
        }
    __syncthreads();
#pragma unroll
    for (int it = 0; it < 8; it++) {
        int u = tid + it * 256;          // 2048 stores of 8 halves
        int g = u >> 4, q = u & 15;
        const float* src = tile + (size_t)g * 132 + q * 8;
        float bi = sbias[g];
        __align__(16) __half h8[8];
#pragma unroll
        for (int i = 0; i < 8; i++) h8[i] = __float2half_rn(src[i] + bi);
        *reinterpret_cast<uint4*>(g_xw + ((size_t)s * G4 + n0 + g) * BSZ + q * 8) =
            *reinterpret_cast<const uint4*>(h8);
    }
}

// ---------------------------------------------------------------------------
// Phase 2: PERSISTENT recurrence (R13 structure; per-half barrier; xw prefetch
// hoisted to before the barrier wait).
// 128 CTAs: j = bid>>1 (16 hidden cols), mh = bid&1 (batch half).
// The two batch halves never exchange data -> two independent 64-CTA barriers.
// smem: B 0..139264 | A 139264 (3x17408) | XW 191488 (2x8192) = 207872
// epilogue overlays: sg f32[64][65] @A buf0, sh f32[64][16] @A buf2
// ---------------------------------------------------------------------------
#define PITCH2   272
#define PB_STG   17408
#define PA_OFF   139264
#define PXW_OFF  191488
#define P2_SMEM  207872
#define NCH2     8

__global__ __launch_bounds__(256, 1) void lstm_persist() {
    extern __shared__ char sm[];
    const uint32_t sb = smem_u32(sm);
    const int tid = threadIdx.x;
    const int wid = tid >> 5, lane = tid & 31;
    const int bid = blockIdx.x;
    const int j  = bid >> 1;
    const int mh = bid & 1;

    const int wm = wid >> 2, gi = wid & 3;
    const int lrow = tid >> 4, lq = tid & 15;   // 16 rows x 16 quads

    const uint32_t a_r = (uint32_t)(lane & 15) * PITCH2 + ((lane >> 4) << 4);
    const uint32_t b_r = (uint32_t)((lane & 7) + ((lane & 16) >> 1)) * PITCH2
                       + (((lane >> 3) & 1) << 4);

    auto xw_load = [&](int t, int slot) {
#pragma unroll
        for (int it = 0; it < 2; it++) {
            int u = tid + it * 256;          // 512 CP16 = 8KB fp16 slice
            int r = u >> 3, q = u & 7;
            const __half* src = g_xw
                + ((size_t)t * G4 + (r >> 4) * HSZ + j * 16 + (r & 15)) * BSZ
                + mh * 64 + q * 8;
            CP16(sb + PXW_OFF + slot * 8192 + r * 128 + q * 16, src);
        }
    };

    // ---- one-time: resident Whh slice (8 chunks) + xw(0) ----
    for (int c = 0; c < NCH2; c++) {
        const int koff = c * 128 + lq * 8;
        uint32_t Sb = sb + c * PB_STG + lrow * PITCH2 + lq * 16;
#pragma unroll
        for (int i = 0; i < 4; i++) {
            int row = lrow + i * 16;
            int grow = (row >> 4) * HSZ + j * 16 + (row & 15);
            CP16(Sb + i * 16 * PITCH2, g_whh + ((size_t)grow << 10) + koff);
        }
    }
    xw_load(0, 0);
    CP_COMMIT();
    CP_WAIT0();
    __syncthreads();

    __shared__ unsigned s_gen;
    if (tid == 0) s_gen = *(volatile unsigned*)&g_bar_gen[mh];
    __syncthreads();
    unsigned gen = s_gen;

    // cell state in registers: thread owns (bl, hq) -> 4 hidden cols
    const int bl = tid & 63, hq = tid >> 6;
    float cre[4] = {0.0f, 0.0f, 0.0f, 0.0f};

    float* sg = reinterpret_cast<float*>(sm + PA_OFF);                 // A buf0
    float* sh = reinterpret_cast<float*>(sm + PA_OFF + 2 * PB_STG);    // A buf2

    for (int t = 0; t < SSZ; t++) {
        if (t > 0) {
            // per-half grid barrier: h(t) rows of this half must be visible
            __syncthreads();
            if (tid == 0) {
                __threadfence();
                unsigned arrived = atomicAdd(&g_bar_count[mh], 1u);
                if (arrived == HALF2 - 1) {
                    *(volatile unsigned*)&g_bar_count[mh] = 0;
                    __threadfence();
                    atomicAdd(&g_bar_gen[mh], 1u);
                } else {
                    while (*(volatile unsigned*)&g_bar_gen[mh] == gen) { __nanosleep(32); }
                    __threadfence();
                }
            }
            __syncthreads();
            gen++;
        }

        const __half* __restrict__ hin = g_h[t & 1];
        __half* __restrict__ hout = g_h[(t + 1) & 1];

        auto loadA = [&](int c, int buf) {
            const int koff = c * 128 + lq * 8;
            uint32_t Sb = sb + PA_OFF + buf * PB_STG + lrow * PITCH2 + lq * 16;
#pragma unroll
            for (int i = 0; i < 4; i++) {
                int row = lrow + i * 16;
                CP16(Sb + i * 16 * PITCH2, hin + ((size_t)(mh * 64 + row) << 10) + koff);
            }
        };

        loadA(0, 0); CP_COMMIT();
        loadA(1, 1); CP_COMMIT();

        float d[2][2][4];
#pragma unroll
        for (int i = 0; i < 2; i++)
#pragma unroll
            for (int jj = 0; jj < 2; jj++)
#pragma unroll
                for (int k = 0; k < 4; k++) d[i][jj][k] = 0.0f;

        int buf = 0;
        for (int c = 0; c < NCH2; c++) {
            CP_WAIT1();
            __syncthreads();
            if (c + 2 < NCH2) loadA(c + 2, (c + 2) % 3);
            CP_COMMIT();
            const uint32_t Hb = sb + PA_OFF + buf * PB_STG;
            const uint32_t Bb = sb + c * PB_STG;     // resident Whh chunk c
#pragma unroll
            for (int s2 = 0; s2 < 8; s2++) {
                uint32_t a[2][4], b[4];
#pragma unroll
                for (int mt = 0; mt < 2; mt++)
                    ldmx4(a[mt], Hb + (uint32_t)(wm * 32 + mt * 16) * PITCH2 + s2 * 32 + a_r);
                ldmx4(b, Bb + (uint32_t)(gi * 16) * PITCH2 + s2 * 32 + b_r);
#pragma unroll
                for (int mt = 0; mt < 2; mt++)
#pragma unroll
                    for (int n8 = 0; n8 < 2; n8++)
                        mma16816(d[mt][n8], a[mt], &b[n8 * 2]);
            }
            buf = (buf == 2) ? 0 : buf + 1;
        }

        // gates to smem: sg[b][gate*16+hc] in A-buf0 (chunk 7 reads buf1)
        const int fr = lane >> 2, fc = (lane & 3) * 2;
#pragma unroll
        for (int mt = 0; mt < 2; mt++)
#pragma unroll
            for (int n8 = 0; n8 < 2; n8++) {
                int r0 = wm * 32 + mt * 16 + fr;
                int cc = gi * 16 + n8 * 8 + fc;
                sg[(size_t)r0 * 65 + cc]           = d[mt][n8][0];
                sg[(size_t)r0 * 65 + cc + 1]       = d[mt][n8][1];
                sg[(size_t)(r0 + 8) * 65 + cc]     = d[mt][n8][2];
                sg[(size_t)(r0 + 8) * 65 + cc + 1] = d[mt][n8][3];
            }
        __syncthreads();

        // fused gate math; c in registers; xw from fp16 smem slot t&1
        const __half* sxwh = reinterpret_cast<const __half*>(sm + PXW_OFF + (t & 1) * 8192);
#pragma unroll
        for (int ii = 0; ii < 4; ii++) {
            const int hc = hq * 4 + ii;
            const size_t ix = (size_t)bl * 65 + hc;
            float vi = sg[ix]      + __half2float(sxwh[(0 * 16 + hc) * 64 + bl]);
            float vf = sg[ix + 16] + __half2float(sxwh[(1 * 16 + hc) * 64 + bl]);
            float vg = sg[ix + 32] + __half2float(sxwh[(2 * 16 + hc) * 64 + bl]);
            float vo = sg[ix + 48] + __half2float(sxwh[(3 * 16 + hc) * 64 + bl]);
            float ig = sigf(vi), fg = sigf(vf), og = sigf(vo);
            float ch = tanh_fast(vg);
            float cn = cre[ii] * fg + ig * ch;
            cre[ii] = cn;
            sh[bl * 16 + hc] = og * tanh_fast(cn);
        }
        __syncthreads();

        // h writeout: fp16, 16B stores
        if (tid < 128) {
            const int b = tid >> 1, half = tid & 1;
            const float* src = sh + b * 16 + half * 8;
            __align__(16) __half h8[8];
#pragma unroll
            for (int i = 0; i < 8; i++) h8[i] = __float2half_rn(src[i]);
            size_t dst = ((size_t)(mh * 64 + b) << 10) + j * 16 + half * 8;
            *reinterpret_cast<uint4*>(hout + dst) = *reinterpret_cast<const uint4*>(h8);
        }

        // prefetch xw(t+1) NOW -- depends only on phase-1 output; its L2
        // latency hides under the upcoming barrier wait. Slot (t+1)&1 was
        // last read in step t-1's gate math, so it's free.
        if (t + 1 < SSZ) { xw_load(t + 1, (t + 1) & 1); CP_COMMIT(); }
    }
}

// ---------------------------------------------------------------------------
// Phase 3: out[b][c] = h_last . Wfc[c] + bfc[c]
// ---------------------------------------------------------------------------
__global__ __launch_bounds__(256) void fc_out(const float* __restrict__ Wfc,
                                              const float* __restrict__ bfc,
                                              float* __restrict__ out) {
    __shared__ float hs[HSZ];
    const int b = blockIdx.x;
    for (int i = threadIdx.x; i < HSZ; i += 256)
        hs[i] = __half2float(g_h[0][b * HSZ + i]);
    __syncthreads();

    for (int cc = threadIdx.x; cc < CSZ; cc += 256) {
        const float* wr = Wfc + (size_t)cc * HSZ;
        float acc = 0.0f;
#pragma unroll 4
        for (int k = 0; k < HSZ; k += 4) {
            float4 w = *reinterpret_cast<const float4*>(wr + k);
            acc = fmaf(hs[k + 0], w.x, acc);
            acc = fmaf(hs[k + 1], w.y, acc);
            acc = fmaf(hs[k + 2], w.z, acc);
            acc = fmaf(hs[k + 3], w.w, acc);
        }
        out[b * CSZ + cc] = acc + bfc[cc];
    }
}

// ---------------------------------------------------------------------------
// launch
// ---------------------------------------------------------------------------
extern "C" void kernel_launch(void* const* d_in, const int* in_sizes, int n_in,
                              void* d_out, int out_size) {
    const float* x   = (const float*)d_in[0];
    const float* Wxh = (const float*)d_in[1];
    const float* bxh = (const float*)d_in[2];
    const float* Whh = (const float*)d_in[3];
    const float* bhh = (const float*)d_in[4];
    const float* Wfc = (const float*)d_in[5];
    const float* bfc = (const float*)d_in[6];
    float* out = (float*)d_out;

    cudaFuncSetAttribute(gemm_xw_tc,   cudaFuncAttributeMaxDynamicSharedMemorySize, P1_SMEM);
    cudaFuncSetAttribute(lstm_persist, cudaFuncAttributeMaxDynamicSharedMemorySize, P2_SMEM);

    {
        int n4 = (BSZ * SSZ * ISZ) / 4;
        round_h16<<<(n4 + 255) / 256, 256>>>(x, 0, n4);
        n4 = (G4 * ISZ) / 4;
        round_h16<<<(n4 + 255) / 256, 256>>>(Wxh, 1, n4);
        n4 = (G4 * HSZ) / 4;
        round_h16<<<(n4 + 255) / 256, 256>>>(Whh, 2, n4);
    }
    init_state<<<(BSZ * HSZ + 255) / 256, 256>>>();

    dim3 g1(G4 / 128, SSZ);   // (32, 256)
    gemm_xw_tc<<<g1, 256, P1_SMEM>>>(bxh, bhh);

    lstm_persist<<<GRID2, 256, P2_SMEM>>>();

    fc_out<<<BSZ, 256>>>(Wfc, bfc, out);
}

// round 16
// speedup vs baseline: 1.1889x; 1.0089x over previous
#include <cuda_runtime.h>
#include <cuda_fp16.h>
#include <cstdint>
#include <math.h>

#define BSZ 128
#define SSZ 256
#define ISZ 1024
#define HSZ 1024
#define G4  4096
#define CSZ 1000

#define GRID2 128
#define HALF2 64     // CTAs per batch-half barrier

// ---------------------------------------------------------------------------
// Device-global scratch
// ---------------------------------------------------------------------------
__device__ __half g_xw[(size_t)SSZ * G4 * BSZ];       // [s][g][b] fp16
__device__ __half g_xh[(size_t)BSZ * SSZ * ISZ];      // x rounded fp16 [b][s][k]
__device__ __half g_wxh[(size_t)G4 * ISZ];            // Wxh rounded fp16
__device__ __half g_whh[(size_t)G4 * HSZ];            // Whh rounded fp16
__device__ __half g_h[2][BSZ * HSZ];                  // h ping-pong fp16 [b][k]
__device__ unsigned g_bar_count[2];                   // per-half barrier (bss)
__device__ unsigned g_bar_gen[2];

// ---------------------------------------------------------------------------
// PTX helpers
// ---------------------------------------------------------------------------
__device__ __forceinline__ uint32_t smem_u32(const void* p) {
    uint32_t a;
    asm("{ .reg .u64 t; cvta.to.shared.u64 t, %1; cvt.u32.u64 %0, t; }"
        : "=r"(a) : "l"(p));
    return a;
}

#define CP16(s, g) \
    asm volatile("cp.async.cg.shared.global [%0], [%1], 16;" :: "r"(s), "l"(g))
#define CP_COMMIT() asm volatile("cp.async.commit_group;" ::: "memory")
#define CP_WAIT1()  asm volatile("cp.async.wait_group 1;" ::: "memory")
#define CP_WAIT0()  asm volatile("cp.async.wait_group 0;" ::: "memory")

__device__ __forceinline__ void ldmx4(uint32_t* r, uint32_t addr) {
    asm volatile("ldmatrix.sync.aligned.m8n8.x4.shared.b16 {%0,%1,%2,%3}, [%4];"
        : "=r"(r[0]), "=r"(r[1]), "=r"(r[2]), "=r"(r[3]) : "r"(addr));
}

__device__ __forceinline__ void mma16816(float* d, const uint32_t* a, const uint32_t* b) {
    asm volatile(
        "mma.sync.aligned.m16n8k16.row.col.f32.f16.f16.f32 "
        "{%0,%1,%2,%3}, {%4,%5,%6,%7}, {%8,%9}, {%0,%1,%2,%3};"
        : "+f"(d[0]), "+f"(d[1]), "+f"(d[2]), "+f"(d[3])
        : "r"(a[0]), "r"(a[1]), "r"(a[2]), "r"(a[3]), "r"(b[0]), "r"(b[1]));
}

__device__ __forceinline__ float sigf(float x) { return 1.0f / (1.0f + __expf(-x)); }
__device__ __forceinline__ float tanh_fast(float x) {
    float e = __expf(fminf(fmaxf(2.0f * x, -30.0f), 30.0f));
    return __fdividef(e - 1.0f, e + 1.0f);
}

// ---------------------------------------------------------------------------
// round fp32 -> fp16
// ---------------------------------------------------------------------------
__global__ void round_h16(const float* __restrict__ src, int sel, int n4) {
    __half* dst = (sel == 0) ? g_xh : (sel == 1) ? g_wxh : g_whh;
    int i = blockIdx.x * blockDim.x + threadIdx.x;
    if (i >= n4) return;
    float4 v = reinterpret_cast<const float4*>(src)[i];
    __half2 a, b;
    a.x = __float2half_rn(v.x); a.y = __float2half_rn(v.y);
    b.x = __float2half_rn(v.z); b.y = __float2half_rn(v.w);
    reinterpret_cast<__half2*>(dst)[2 * i]     = a;
    reinterpret_cast<__half2*>(dst)[2 * i + 1] = b;
}

__global__ void init_state() {
    int i = blockIdx.x * blockDim.x + threadIdx.x;
    if (i < BSZ * HSZ) g_h[0][i] = __float2half(0.0f);
}

// ---------------------------------------------------------------------------
// Phase 1: xw[s][g][b] (fp16), M=128 (batch), N=128 gates/CTA, K=1024, 16 chunks.
// (unchanged -- at the HMMA.f32 roofline)
// ---------------------------------------------------------------------------
#define PITCH     144
#define P1_STG    36864
#define P1_BOFF   18432
#define P1_BIAS   110592
#define P1_SMEM   111104
#define NCHUNK    16

__global__ __launch_bounds__(256, 1) void gemm_xw_tc(const float* __restrict__ bxh,
                                                     const float* __restrict__ bhh) {
    extern __shared__ char sm[];
    const uint32_t sb = smem_u32(sm);
    const int tid = threadIdx.x;
    const int wid = tid >> 5, lane = tid & 31;
    const int s  = blockIdx.y;
    const int n0 = blockIdx.x * 128;

    float* sbias = reinterpret_cast<float*>(sm + P1_BIAS);
    if (tid < 128) sbias[tid] = bxh[n0 + tid] + bhh[n0 + tid];

    const int wm = wid >> 2, wn = wid & 3;
    const int lrow = tid >> 3, lq = tid & 7;

    auto load_stage = [&](int c, int buf) {
        const int koff = c * 64 + lq * 8;
        uint32_t Ab = sb + buf * P1_STG + lrow * PITCH + lq * 16;
        uint32_t Bb = Ab + P1_BOFF;
#pragma unroll
        for (int i = 0; i < 4; i++) {
            int row = lrow + i * 32;
            CP16(Ab + i * 32 * PITCH, g_xh + (((size_t)((row << 8) + s)) << 10) + koff);
            CP16(Bb + i * 32 * PITCH, g_wxh + (((size_t)(n0 + row)) << 10) + koff);
        }
    };

    load_stage(0, 0); CP_COMMIT();
    load_stage(1, 1); CP_COMMIT();

    float d[4][4][4];
#pragma unroll
    for (int i = 0; i < 4; i++)
#pragma unroll
        for (int j = 0; j < 4; j++)
#pragma unroll
            for (int k = 0; k < 4; k++) d[i][j][k] = 0.0f;

    const uint32_t a_r = (uint32_t)(lane & 15) * PITCH + ((lane >> 4) << 4);
    const uint32_t b_r = (uint32_t)((lane & 7) + ((lane & 16) >> 1)) * PITCH
                       + (((lane >> 3) & 1) << 4);

    int buf = 0;
    for (int c = 0; c < NCHUNK; c++) {
        CP_WAIT1();
        __syncthreads();
        if (c + 2 < NCHUNK) load_stage(c + 2, (c + 2) % 3);
        CP_COMMIT();
        const uint32_t Ab = sb + buf * P1_STG;
        const uint32_t Bb = Ab + P1_BOFF;
#pragma unroll
        for (int s2 = 0; s2 < 4; s2++) {
            uint32_t a[4][4], b[2][4];
#pragma unroll
            for (int mt = 0; mt < 4; mt++)
                ldmx4(a[mt], Ab + (uint32_t)(wm * 64 + mt * 16) * PITCH + s2 * 32 + a_r);
#pragma unroll
            for (int nt = 0; nt < 2; nt++)
                ldmx4(b[nt], Bb + (uint32_t)(wn * 32 + nt * 16) * PITCH + s2 * 32 + b_r);
#pragma unroll
            for (int mt = 0; mt < 4; mt++)
#pragma unroll
                for (int n8 = 0; n8 < 4; n8++)
                    mma16816(d[mt][n8], a[mt], &b[n8 >> 1][(n8 & 1) * 2]);
        }
        buf = (buf == 2) ? 0 : buf + 1;
    }

    // epilogue: transpose through smem, fp16 writeout with bias
    __syncthreads();
    float* tile = reinterpret_cast<float*>(sm);  // [g:128][pitch 132]
    const int fr = lane >> 2, fc = (lane & 3) * 2;
#pragma unroll
    for (int mt = 0; mt < 4; mt++)
#pragma unroll
        for (int n8 = 0; n8 < 4; n8++) {
            int r0 = wm * 64 + mt * 16 + fr;
            int cc = wn * 32 + n8 * 8 + fc;
            tile[(size_t)cc * 132 + r0]           = d[mt][n8][0];
            tile[(size_t)(cc + 1) * 132 + r0]     = d[mt][n8][1];
            tile[(size_t)cc * 132 + r0 + 8]       = d[mt][n8][2];
            tile[(size_t)(cc + 1) * 132 + r0 + 8] = d[mt][n8][3];
        }
    __syncthreads();
#pragma unroll
    for (int it = 0; it < 8; it++) {
        int u = tid + it * 256;          // 2048 stores of 8 halves
        int g = u >> 4, q = u & 15;
        const float* src = tile + (size_t)g * 132 + q * 8;
        float bi = sbias[g];
        __align__(16) __half h8[8];
#pragma unroll
        for (int i = 0; i < 8; i++) h8[i] = __float2half_rn(src[i] + bi);
        *reinterpret_cast<uint4*>(g_xw + ((size_t)s * G4 + n0 + g) * BSZ + q * 8) =
            *reinterpret_cast<const uint4*>(h8);
    }
}

// ---------------------------------------------------------------------------
// Phase 2: PERSISTENT recurrence (R15 base + GATE-INTERLEAVED B mapping).
// 128 CTAs: j = bid>>1 (16 hidden cols), mh = bid&1 (batch half).
// B (Whh) N-columns reordered so each thread's accumulator fragment holds all
// 4 gates of one (b-row, hc): local col rem = 2*hcl + (g&1) + 8*(g>>1).
// Gate math runs directly on registers -- no smem transpose, 2 fewer syncs.
// xw smem slots use pitch 72 halves (144B) for conflict-free strided reads.
// smem: B 0..139264 | A 139264 (3x17408) | XW 191488 (2x9216) = 209920
// epilogue overlay: sh f32[64][16] @A buf2
// ---------------------------------------------------------------------------
#define PITCH2   272
#define PB_STG   17408
#define PA_OFF   139264
#define PXW_OFF  191488
#define XW_SLOT  9216
#define XWP      72          // xw slot pitch in halves
#define P2_SMEM  209920
#define NCH2     8

__global__ __launch_bounds__(256, 1) void lstm_persist() {
    extern __shared__ char sm[];
    const uint32_t sb = smem_u32(sm);
    const int tid = threadIdx.x;
    const int wid = tid >> 5, lane = tid & 31;
    const int bid = blockIdx.x;
    const int j  = bid >> 1;
    const int mh = bid & 1;

    const int wm = wid >> 2, gi = wid & 3;
    const int lrow = tid >> 4, lq = tid & 15;   // 16 rows x 16 quads

    const uint32_t a_r = (uint32_t)(lane & 15) * PITCH2 + ((lane >> 4) << 4);
    const uint32_t b_r = (uint32_t)((lane & 7) + ((lane & 16) >> 1)) * PITCH2
                       + (((lane >> 3) & 1) << 4);

    auto xw_load = [&](int t, int slot) {
#pragma unroll
        for (int it = 0; it < 2; it++) {
            int u = tid + it * 256;          // 512 CP16 = 8KB fp16 slice
            int r = u >> 3, q = u & 7;
            const __half* src = g_xw
                + ((size_t)t * G4 + (r >> 4) * HSZ + j * 16 + (r & 15)) * BSZ
                + mh * 64 + q * 8;
            CP16(sb + PXW_OFF + slot * XW_SLOT + r * (XWP * 2) + q * 16, src);
        }
    };

    // ---- one-time: resident Whh slice with GATE-INTERLEAVED row order ----
    // local N index r: rem=r&15 -> gate = (rem&1)+2*((rem>>3)&1), hcl=(rem>>1)&3
    // global row = gate*HSZ + j*16 + (r>>4)*4 + hcl
    for (int c = 0; c < NCH2; c++) {
        const int koff = c * 128 + lq * 8;
        uint32_t Sb = sb + c * PB_STG + lrow * PITCH2 + lq * 16;
#pragma unroll
        for (int i = 0; i < 4; i++) {
            int row = lrow + i * 16;
            int rem = row & 15;
            int gg  = (rem & 1) + 2 * ((rem >> 3) & 1);
            int hcl = (rem >> 1) & 3;
            int grow = gg * HSZ + j * 16 + (row >> 4) * 4 + hcl;
            CP16(Sb + i * 16 * PITCH2, g_whh + ((size_t)grow << 10) + koff);
        }
    }
    xw_load(0, 0);
    CP_COMMIT();
    CP_WAIT0();
    __syncthreads();

    __shared__ unsigned s_gen;
    if (tid == 0) s_gen = *(volatile unsigned*)&g_bar_gen[mh];
    __syncthreads();
    unsigned gen = s_gen;

    // cell state in registers: thread owns 4 b-rows x 1 hidden col
    // rows: wm*32 + mt*16 + fr (+8), mt in {0,1}; hc16 = gi*4 + (lane&3)
    const int fr = lane >> 2;
    const int hc16 = gi * 4 + (lane & 3);
    float cre[4] = {0.0f, 0.0f, 0.0f, 0.0f};

    float* sh = reinterpret_cast<float*>(sm + PA_OFF + 2 * PB_STG);    // A buf2

    for (int t = 0; t < SSZ; t++) {
        if (t > 0) {
            // per-half grid barrier: h(t) rows of this half must be visible
            __syncthreads();
            if (tid == 0) {
                __threadfence();
                unsigned arrived = atomicAdd(&g_bar_count[mh], 1u);
                if (arrived == HALF2 - 1) {
                    *(volatile unsigned*)&g_bar_count[mh] = 0;
                    __threadfence();
                    atomicAdd(&g_bar_gen[mh], 1u);
                } else {
                    while (*(volatile unsigned*)&g_bar_gen[mh] == gen) { __nanosleep(32); }
                    __threadfence();
                }
            }
            __syncthreads();
            gen++;
        }

        const __half* __restrict__ hin = g_h[t & 1];
        __half* __restrict__ hout = g_h[(t + 1) & 1];

        auto loadA = [&](int c, int buf) {
            const int koff = c * 128 + lq * 8;
            uint32_t Sb = sb + PA_OFF + buf * PB_STG + lrow * PITCH2 + lq * 16;
#pragma unroll
            for (int i = 0; i < 4; i++) {
                int row = lrow + i * 16;
                CP16(Sb + i * 16 * PITCH2, hin + ((size_t)(mh * 64 + row) << 10) + koff);
            }
        };

        loadA(0, 0); CP_COMMIT();
        loadA(1, 1); CP_COMMIT();

        float d[2][2][4];
#pragma unroll
        for (int i = 0; i < 2; i++)
#pragma unroll
            for (int jj = 0; jj < 2; jj++)
#pragma unroll
                for (int k = 0; k < 4; k++) d[i][jj][k] = 0.0f;

        int buf = 0;
        for (int c = 0; c < NCH2; c++) {
            CP_WAIT1();
            __syncthreads();
            if (c + 2 < NCH2) loadA(c + 2, (c + 2) % 3);
            CP_COMMIT();
            const uint32_t Hb = sb + PA_OFF + buf * PB_STG;
            const uint32_t Bb = sb + c * PB_STG;     // resident Whh chunk c
#pragma unroll
            for (int s2 = 0; s2 < 8; s2++) {
                uint32_t a[2][4], b[4];
#pragma unroll
                for (int mt = 0; mt < 2; mt++)
                    ldmx4(a[mt], Hb + (uint32_t)(wm * 32 + mt * 16) * PITCH2 + s2 * 32 + a_r);
                ldmx4(b, Bb + (uint32_t)(gi * 16) * PITCH2 + s2 * 32 + b_r);
#pragma unroll
                for (int mt = 0; mt < 2; mt++)
#pragma unroll
                    for (int n8 = 0; n8 < 2; n8++)
                        mma16816(d[mt][n8], a[mt], &b[n8 * 2]);
            }
            buf = (buf == 2) ? 0 : buf + 1;
        }

        // gate math DIRECTLY on fragments (per thread: 4 b-rows x 1 hc).
        // d[mt][0][rr*2+0]=i, d[mt][0][rr*2+1]=f, d[mt][1][rr*2+0]=g,
        // d[mt][1][rr*2+1]=o for row wm*32+mt*16+fr+rr*8.
        // sh (A buf2) is dead: all warps passed c=7's top barrier (chunk 7
        // reads buf1; buf2 last read at chunk 5).
        const __half* sxwh = reinterpret_cast<const __half*>(sm + PXW_OFF + (t & 1) * XW_SLOT);
#pragma unroll
        for (int mt = 0; mt < 2; mt++)
#pragma unroll
            for (int rr = 0; rr < 2; rr++) {
                const int brow = wm * 32 + mt * 16 + fr + rr * 8;
                const int ci = mt * 2 + rr;
                float vi = d[mt][0][rr * 2]     + __half2float(sxwh[(0 * 16 + hc16) * XWP + brow]);
                float vf = d[mt][0][rr * 2 + 1] + __half2float(sxwh[(1 * 16 + hc16) * XWP + brow]);
                float vg = d[mt][1][rr * 2]     + __half2float(sxwh[(2 * 16 + hc16) * XWP + brow]);
                float vo = d[mt][1][rr * 2 + 1] + __half2float(sxwh[(3 * 16 + hc16) * XWP + brow]);
                float ig = sigf(vi), fg = sigf(vf), og = sigf(vo);
                float ch = tanh_fast(vg);
                float cn = cre[ci] * fg + ig * ch;
                cre[ci] = cn;
                sh[brow * 16 + hc16] = og * tanh_fast(cn);
            }
        __syncthreads();

        // h writeout: fp16, 16B stores
        if (tid < 128) {
            const int b = tid >> 1, half = tid & 1;
            const float* src = sh + b * 16 + half * 8;
            __align__(16) __half h8[8];
#pragma unroll
            for (int i = 0; i < 8; i++) h8[i] = __float2half_rn(src[i]);
            size_t dst = ((size_t)(mh * 64 + b) << 10) + j * 16 + half * 8;
            *reinterpret_cast<uint4*>(hout + dst) = *reinterpret_cast<const uint4*>(h8);
        }

        // prefetch xw(t+1): depends only on phase-1 output; latency hides
        // under the upcoming barrier wait. Slot (t+1)&1 last read step t-1.
        if (t + 1 < SSZ) { xw_load(t + 1, (t + 1) & 1); CP_COMMIT(); }
    }
}

// ---------------------------------------------------------------------------
// Phase 3: out[b][c] = h_last . Wfc[c] + bfc[c]
// ---------------------------------------------------------------------------
__global__ __launch_bounds__(256) void fc_out(const float* __restrict__ Wfc,
                                              const float* __restrict__ bfc,
                                              float* __restrict__ out) {
    __shared__ float hs[HSZ];
    const int b = blockIdx.x;
    for (int i = threadIdx.x; i < HSZ; i += 256)
        hs[i] = __half2float(g_h[0][b * HSZ + i]);
    __syncthreads();

    for (int cc = threadIdx.x; cc < CSZ; cc += 256) {
        const float* wr = Wfc + (size_t)cc * HSZ;
        float acc = 0.0f;
#pragma unroll 4
        for (int k = 0; k < HSZ; k += 4) {
            float4 w = *reinterpret_cast<const float4*>(wr + k);
            acc = fmaf(hs[k + 0], w.x, acc);
            acc = fmaf(hs[k + 1], w.y, acc);
            acc = fmaf(hs[k + 2], w.z, acc);
            acc = fmaf(hs[k + 3], w.w, acc);
        }
        out[b * CSZ + cc] = acc + bfc[cc];
    }
}

// ---------------------------------------------------------------------------
// launch
// ---------------------------------------------------------------------------
extern "C" void kernel_launch(void* const* d_in, const int* in_sizes, int n_in,
                              void* d_out, int out_size) {
    const float* x   = (const float*)d_in[0];
    const float* Wxh = (const float*)d_in[1];
    const float* bxh = (const float*)d_in[2];
    const float* Whh = (const float*)d_in[3];
    const float* bhh = (const float*)d_in[4];
    const float* Wfc = (const float*)d_in[5];
    const float* bfc = (const float*)d_in[6];
    float* out = (float*)d_out;

    cudaFuncSetAttribute(gemm_xw_tc,   cudaFuncAttributeMaxDynamicSharedMemorySize, P1_SMEM);
    cudaFuncSetAttribute(lstm_persist, cudaFuncAttributeMaxDynamicSharedMemorySize, P2_SMEM);

    {
        int n4 = (BSZ * SSZ * ISZ) / 4;
        round_h16<<<(n4 + 255) / 256, 256>>>(x, 0, n4);
        n4 = (G4 * ISZ) / 4;
        round_h16<<<(n4 + 255) / 256, 256>>>(Wxh, 1, n4);
        n4 = (G4 * HSZ) / 4;
        round_h16<<<(n4 + 255) / 256, 256>>>(Whh, 2, n4);
    }
    init_state<<<(BSZ * HSZ + 255) / 256, 256>>>();

    dim3 g1(G4 / 128, SSZ);   // (32, 256)
    gemm_xw_tc<<<g1, 256, P1_SMEM>>>(bxh, bhh);

    lstm_persist<<<GRID2, 256, P2_SMEM>>>();

    fc_out<<<BSZ, 256>>>(Wfc, bfc, out);
}